// round 3
// baseline (speedup 1.0000x reference)
#include <cuda_runtime.h>

// GPT2Editor: softmax over a size-1 axis -> weights == 1, so
// out[s, :] = sum_f ( (h_last @ Wc[f][:, E:2E] + bc[f][E:]) @ Wp[f] + bp[f] )
// broadcast to all 4096 rows. Dead inputs: encoder_hidden_states, Wq, bq.
// E = 2048, F = 4.

#define EDIM 2048
#define FDIM 4
#define SOUT 4096
#define ECHUNK 32
#define NCHUNK (EDIM / ECHUNK)   // 64

__device__ float g_v[FDIM * EDIM];  // v rows, one per f
__device__ float g_r[EDIM];         // final broadcast row

// g_v[f,j] = bc[f, E+j];  g_r[o] = sum_f bp[f, o]
__global__ void init_kernel(const float* __restrict__ bc,
                            const float* __restrict__ bp) {
    int i = blockIdx.x * blockDim.x + threadIdx.x;
    if (i < FDIM * EDIM) {
        int f = i >> 11;
        int j = i & (EDIM - 1);
        g_v[i] = bc[f * 2 * EDIM + EDIM + j];
    }
    if (i < EDIM) {
        float s = 0.0f;
#pragma unroll
        for (int f = 0; f < FDIM; f++) s += bp[f * EDIM + i];
        g_r[i] = s;
    }
}

// v[f, j..j+3] += sum_{e in 32-chunk} h_last[e] * Wc[f, e, E + j..j+3]
// grid: (EDIM/1024, NCHUNK, F) = (2, 64, 4) = 512 blocks, block 256.
__global__ void __launch_bounds__(256)
gemv_v_kernel(const float* __restrict__ h_last,
              const float* __restrict__ Wc) {
    __shared__ float sh[ECHUNK];
    const int f  = blockIdx.z;
    const int j  = blockIdx.x * 1024 + threadIdx.x * 4;
    const int e0 = blockIdx.y * ECHUNK;

    if (threadIdx.x < ECHUNK) sh[threadIdx.x] = h_last[e0 + threadIdx.x];
    __syncthreads();

    const float* W =
        Wc + ((size_t)f * EDIM + e0) * (2 * EDIM) + EDIM + j;
    float4 acc = make_float4(0.f, 0.f, 0.f, 0.f);
#pragma unroll 16
    for (int e = 0; e < ECHUNK; e++) {
        float4 w = *reinterpret_cast<const float4*>(W + (size_t)e * (2 * EDIM));
        float hv = sh[e];
        acc.x = fmaf(hv, w.x, acc.x);
        acc.y = fmaf(hv, w.y, acc.y);
        acc.z = fmaf(hv, w.z, acc.z);
        acc.w = fmaf(hv, w.w, acc.w);
    }
    float* dst = &g_v[f * EDIM + j];
    atomicAdd(dst + 0, acc.x);
    atomicAdd(dst + 1, acc.y);
    atomicAdd(dst + 2, acc.z);
    atomicAdd(dst + 3, acc.w);
}

// r[o..o+3] += sum_f sum_{e in 32-chunk} v[f, e] * Wp[f, e, o..o+3]
__global__ void __launch_bounds__(256)
gemv_r_kernel(const float* __restrict__ Wp) {
    __shared__ float sv[ECHUNK];
    const int f  = blockIdx.z;
    const int o  = blockIdx.x * 1024 + threadIdx.x * 4;
    const int e0 = blockIdx.y * ECHUNK;

    if (threadIdx.x < ECHUNK) sv[threadIdx.x] = g_v[f * EDIM + e0 + threadIdx.x];
    __syncthreads();

    const float* W = Wp + ((size_t)f * EDIM + e0) * EDIM + o;
    float4 acc = make_float4(0.f, 0.f, 0.f, 0.f);
#pragma unroll 16
    for (int e = 0; e < ECHUNK; e++) {
        float4 w = *reinterpret_cast<const float4*>(W + (size_t)e * EDIM);
        float vv = sv[e];
        acc.x = fmaf(vv, w.x, acc.x);
        acc.y = fmaf(vv, w.y, acc.y);
        acc.z = fmaf(vv, w.z, acc.z);
        acc.w = fmaf(vv, w.w, acc.w);
    }
    float* dst = &g_r[o];
    atomicAdd(dst + 0, acc.x);
    atomicAdd(dst + 1, acc.y);
    atomicAdd(dst + 2, acc.z);
    atomicAdd(dst + 3, acc.w);
}

// out[s, :] = r[:] for 4 rows per block; grid 1024 blocks.
__global__ void __launch_bounds__(256)
bcast_kernel(float4* __restrict__ out) {
    const float4* r4 = reinterpret_cast<const float4*>(g_r);
    float4 a = r4[threadIdx.x];
    float4 b = r4[threadIdx.x + 256];
    size_t base = (size_t)blockIdx.x * 4 * 512;
#pragma unroll
    for (int s = 0; s < 4; s++) {
        out[base + (size_t)s * 512 + threadIdx.x]       = a;
        out[base + (size_t)s * 512 + threadIdx.x + 256] = b;
    }
}

extern "C" void kernel_launch(void* const* d_in, const int* in_sizes, int n_in,
                              void* d_out, int out_size) {
    // order: hidden_states, encoder_hidden_states, Wq, bq, Wc, bc, Wp, bp
    const float* hidden = (const float*)d_in[0];
    const float* Wc     = (const float*)d_in[4];
    const float* bc     = (const float*)d_in[5];
    const float* Wp     = (const float*)d_in[6];
    const float* bp     = (const float*)d_in[7];
    float* out = (float*)d_out;

    const float* h_last = hidden + 127 * EDIM;  // hidden_states[0, -1, :]

    init_kernel<<<(FDIM * EDIM + 255) / 256, 256>>>(bc, bp);
    gemv_v_kernel<<<dim3(EDIM / 1024, NCHUNK, FDIM), 256>>>(h_last, Wc);
    gemv_r_kernel<<<dim3(EDIM / 1024, NCHUNK, FDIM), 256>>>(Wp);
    bcast_kernel<<<SOUT / 4, 256>>>((float4*)out);
}

// round 4
// speedup vs baseline: 1.0955x; 1.0955x over previous
#include <cuda_runtime.h>

// GPT2Editor: softmax over a size-1 axis -> weights == 1, so
// out[s, :] = sum_f ( (h_last @ Wc[f][:, E:2E] + bc[f][E:]) @ Wp[f] + bp[f] )
// broadcast to all 4096 rows. Dead inputs: encoder_hidden_states, Wq, bq.
// E = 2048, F = 4.

#define EDIM 2048
#define FDIM 4
#define SOUT 4096
#define ECHUNK 64
#define NCHUNK (EDIM / ECHUNK)   // 32

__device__ float g_v[FDIM * EDIM];  // v rows, one per f
__device__ float g_r[EDIM];         // final broadcast row
__device__ float g_dummy[32];

// Profiling-rotation dummy: shifts which kernel lands on ncu's sampled
// launch ordinal so we finally get a GEMV profile instead of bcast.
__global__ void dummy_kernel() {
    g_dummy[threadIdx.x] = (float)threadIdx.x;
}

// g_v[f,j] = bc[f, E+j];  g_r[o] = sum_f bp[f, o]
__global__ void init_kernel(const float* __restrict__ bc,
                            const float* __restrict__ bp) {
    int i = blockIdx.x * blockDim.x + threadIdx.x;
    if (i < FDIM * EDIM) {
        int f = i >> 11;
        int j = i & (EDIM - 1);
        g_v[i] = bc[f * 2 * EDIM + EDIM + j];
    }
    if (i < EDIM) {
        float s = 0.0f;
#pragma unroll
        for (int f = 0; f < FDIM; f++) s += bp[f * EDIM + i];
        g_r[i] = s;
    }
}

// v[f, j] += sum_{e in 64-chunk} h_last[e] * Wc[f, e, E + j]
// grid: (EDIM/256, NCHUNK, F) = (8, 32, 4) = 1024 blocks, block 256.
__global__ void __launch_bounds__(256)
gemv_v_kernel(const float* __restrict__ h_last,
              const float* __restrict__ Wc) {
    __shared__ float sh[ECHUNK];
    const int f  = blockIdx.z;
    const int j  = blockIdx.x * 256 + threadIdx.x;
    const int e0 = blockIdx.y * ECHUNK;

    if (threadIdx.x < ECHUNK) sh[threadIdx.x] = h_last[e0 + threadIdx.x];
    __syncthreads();

    const float* W = Wc + ((size_t)f * EDIM + e0) * (2 * EDIM) + EDIM + j;
    float acc = 0.0f;
#pragma unroll 16
    for (int e = 0; e < ECHUNK; e++) {
        acc = fmaf(sh[e], W[(size_t)e * (2 * EDIM)], acc);
    }
    atomicAdd(&g_v[f * EDIM + j], acc);
}

// r[o] += sum_f sum_{e in 64-chunk} v[f, e] * Wp[f, e, o]
__global__ void __launch_bounds__(256)
gemv_r_kernel(const float* __restrict__ Wp) {
    __shared__ float sv[ECHUNK];
    const int f  = blockIdx.z;
    const int o  = blockIdx.x * 256 + threadIdx.x;
    const int e0 = blockIdx.y * ECHUNK;

    if (threadIdx.x < ECHUNK) sv[threadIdx.x] = g_v[f * EDIM + e0 + threadIdx.x];
    __syncthreads();

    const float* W = Wp + ((size_t)f * EDIM + e0) * EDIM + o;
    float acc = 0.0f;
#pragma unroll 16
    for (int e = 0; e < ECHUNK; e++) {
        acc = fmaf(sv[e], W[(size_t)e * EDIM], acc);
    }
    atomicAdd(&g_r[o], acc);
}

// out[s, :] = r[:]; grid SOUT blocks, each block writes one 2048-float row.
__global__ void __launch_bounds__(256)
bcast_kernel(float4* __restrict__ out) {
    const float4* r4 = reinterpret_cast<const float4*>(g_r);
    const size_t s = blockIdx.x;
    float4 a = r4[threadIdx.x];
    float4 b = r4[threadIdx.x + 256];
    out[s * 512 + threadIdx.x]       = a;
    out[s * 512 + threadIdx.x + 256] = b;
}

extern "C" void kernel_launch(void* const* d_in, const int* in_sizes, int n_in,
                              void* d_out, int out_size) {
    // order: hidden_states, encoder_hidden_states, Wq, bq, Wc, bc, Wp, bp
    const float* hidden = (const float*)d_in[0];
    const float* Wc     = (const float*)d_in[4];
    const float* bc     = (const float*)d_in[5];
    const float* Wp     = (const float*)d_in[6];
    const float* bp     = (const float*)d_in[7];
    float* out = (float*)d_out;

    const float* h_last = hidden + 127 * EDIM;  // hidden_states[0, -1, :]

    dummy_kernel<<<1, 32>>>();
    init_kernel<<<(FDIM * EDIM + 255) / 256, 256>>>(bc, bp);
    gemv_v_kernel<<<dim3(EDIM / 256, NCHUNK, FDIM), 256>>>(h_last, Wc);
    gemv_r_kernel<<<dim3(EDIM / 256, NCHUNK, FDIM), 256>>>(Wp);
    bcast_kernel<<<SOUT, 256>>>((float4*)out);
}